// round 8
// baseline (speedup 1.0000x reference)
#include <cuda_runtime.h>
#include <cuda_fp16.h>

#define ALPHA 0.2f
#define MAXN 100000
#define MAXE 1600000
// F=128, H=8, D=16, C=H*D=128

typedef unsigned long long ull;

__device__ __half g_whh[(size_t)MAXN * 128]; // projected features [N][128] fp16
__device__ float  g_s1[(size_t)MAXN * 8];
__device__ float  g_s2[(size_t)MAXN * 8];
__device__ int    g_cnt[MAXN];               // per-dst counts / fill cursor
__device__ int    g_off[MAXN + 1];           // CSR offsets by dst
__device__ int    g_esrc[MAXE];              // src node id per CSR slot
__device__ int    g_part[512];               // scan partials

__device__ __forceinline__ float lrelu(float x) {
    return x > 0.f ? x : ALPHA * x;
}

#define FMA2(d, a, b) asm("fma.rn.f32x2 %0, %1, %2, %0;" : "+l"(d) : "l"(a), "l"(b))
#define PACK2(o, lo, hi) asm("mov.b64 %0, {%1, %2};" : "=l"(o) : "f"(lo), "f"(hi))
#define UNPACK2(lo, hi, in) asm("mov.b64 {%0, %1}, %2;" : "=f"(lo), "=f"(hi) : "l"(in))

// ---------------------------------------------------------------- zero counts
__global__ void zcntk(int N) {
    int i = blockIdx.x * blockDim.x + threadIdx.x;
    if (i < N) g_cnt[i] = 0;
}

// ---------------------------------------------------------------- projection + fused s1/s2
// 128 nodes per block, 256 threads, 8x8 register tile per thread via f32x2 FMA.
__global__ void __launch_bounds__(256) projk(const float* __restrict__ h,
                                             const float* __restrict__ W,
                                             const float* __restrict__ a1,
                                             const float* __restrict__ a2,
                                             int N) {
    extern __shared__ float sm[];
    float* ws  = sm;            // 16384 floats: W transposed [k][c]
    float* hst = sm + 16384;    // 16384 floats: h transposed [k][n_local]
    int tid = threadIdx.x;
    int n0 = blockIdx.x * 128;

    for (int idx = tid; idx < 16384; idx += 256) {
        int k = idx >> 7, c = idx & 127;
        ws[idx] = W[(c >> 4) * 2048 + k * 16 + (c & 15)];
    }
    {
        int i = tid >> 1, kh = tid & 1;   // node i, k-half kh
        int n = n0 + i;
#pragma unroll
        for (int j = 0; j < 16; j++) {
            int k = kh * 64 + j * 4;
            float4 v = make_float4(0.f, 0.f, 0.f, 0.f);
            if (n < N) v = *(const float4*)&h[(size_t)n * 128 + k];
            hst[(k + 0) * 128 + i] = v.x;
            hst[(k + 1) * 128 + i] = v.y;
            hst[(k + 2) * 128 + i] = v.z;
            hst[(k + 3) * 128 + i] = v.w;
        }
    }
    __syncthreads();

    int cg = tid & 15;   // cols cg*8 .. cg*8+7
    int ng = tid >> 4;   // nodes ng*8 .. ng*8+7
    ull accp[8][4];      // [node][col-pair], f32x2 accumulators
#pragma unroll
    for (int i = 0; i < 8; i++)
#pragma unroll
        for (int j = 0; j < 4; j++) accp[i][j] = 0ull;

#pragma unroll 2
    for (int k = 0; k < 128; k++) {
        ulonglong2 wA = *(const ulonglong2*)&ws[k * 128 + cg * 8];      // cols 0-3
        ulonglong2 wB = *(const ulonglong2*)&ws[k * 128 + cg * 8 + 4];  // cols 4-7
        float4 hA = *(const float4*)&hst[k * 128 + ng * 8];
        float4 hB = *(const float4*)&hst[k * 128 + ng * 8 + 4];
        ull wp[4] = {wA.x, wA.y, wB.x, wB.y};
        float hv[8] = {hA.x, hA.y, hA.z, hA.w, hB.x, hB.y, hB.z, hB.w};
        ull hp[8];
#pragma unroll
        for (int i = 0; i < 8; i++) PACK2(hp[i], hv[i], hv[i]);
#pragma unroll
        for (int i = 0; i < 8; i++)
#pragma unroll
            for (int j = 0; j < 4; j++) FMA2(accp[i][j], hp[i], wp[j]);
    }

    // unpack accumulators
    float acc[8][8];
#pragma unroll
    for (int i = 0; i < 8; i++)
#pragma unroll
        for (int j = 0; j < 4; j++) UNPACK2(acc[i][2 * j], acc[i][2 * j + 1], accp[i][j]);

    // epilogue: store Wh (fp16) + fused s1/s2 (head = cg>>1, half = cg&1)
    int head = cg >> 1;
    float a1v[8], a2v[8];
#pragma unroll
    for (int j = 0; j < 8; j++) {
        a1v[j] = __ldg(&a1[head * 16 + (cg & 1) * 8 + j]);
        a2v[j] = __ldg(&a2[head * 16 + (cg & 1) * 8 + j]);
    }
#pragma unroll
    for (int i = 0; i < 8; i++) {
        float p1 = 0.f, p2 = 0.f;
#pragma unroll
        for (int j = 0; j < 8; j++) {
            p1 += acc[i][j] * a1v[j];
            p2 += acc[i][j] * a2v[j];
        }
        p1 += __shfl_xor_sync(0xffffffffu, p1, 1);
        p2 += __shfl_xor_sync(0xffffffffu, p2, 1);
        int n = n0 + ng * 8 + i;
        if (n < N) {
            __half2 q[4];
#pragma unroll
            for (int j = 0; j < 4; j++)
                q[j] = __floats2half2_rn(acc[i][2 * j], acc[i][2 * j + 1]);
            *(uint4*)&g_whh[(size_t)n * 128 + cg * 8] = *(uint4*)q;
            if (!(cg & 1)) {
                g_s1[(size_t)n * 8 + head] = p1;
                g_s2[(size_t)n * 8 + head] = p2;
            }
        }
    }
}

// ---------------------------------------------------------------- CSR: count (4 edges/thread)
__global__ void countk(const int* __restrict__ dst, int E) {
    int e4 = (blockIdx.x * blockDim.x + threadIdx.x) * 4;
    if (e4 >= E) return;
    if (e4 + 4 <= E) {
        int4 d = *(const int4*)&dst[e4];
        atomicAdd(&g_cnt[d.x], 1);
        atomicAdd(&g_cnt[d.y], 1);
        atomicAdd(&g_cnt[d.z], 1);
        atomicAdd(&g_cnt[d.w], 1);
    } else {
        for (int e = e4; e < E; e++) atomicAdd(&g_cnt[__ldg(&dst[e])], 1);
    }
}

// ---------------------------------------------------------------- scan stage 1: block sums
__global__ void scan1k(int N) {
    __shared__ int wsum[8];
    int b = blockIdx.x;
    int i = b * 256 + threadIdx.x;
    int v = (i < N) ? g_cnt[i] : 0;
#pragma unroll
    for (int o = 16; o; o >>= 1) v += __shfl_down_sync(0xffffffffu, v, o);
    if ((threadIdx.x & 31) == 0) wsum[threadIdx.x >> 5] = v;
    __syncthreads();
    if (threadIdx.x == 0) {
        int s = 0;
#pragma unroll
        for (int k = 0; k < 8; k++) s += wsum[k];
        g_part[b] = s;
    }
}

// ---------------------------------------------------------------- scan stage 2: scan partials (1 block)
__global__ void scan2k(int nb) {
    __shared__ int s2[512];
    int t = threadIdx.x;
    s2[t] = (t < nb) ? g_part[t] : 0;
    __syncthreads();
    for (int o = 1; o < 512; o <<= 1) {
        int v = (t >= o) ? s2[t - o] : 0;
        __syncthreads();
        s2[t] += v;
        __syncthreads();
    }
    if (t < nb) g_part[t] = t ? s2[t - 1] : 0;  // exclusive
}

// ---------------------------------------------------------------- scan stage 3: offsets + cursor reset
__global__ void scan3k(int N, int E) {
    __shared__ int s3[256];
    int b = blockIdx.x, t = threadIdx.x;
    int i = b * 256 + t;
    int c = (i < N) ? g_cnt[i] : 0;
    s3[t] = c;
    __syncthreads();
    for (int o = 1; o < 256; o <<= 1) {
        int v = (t >= o) ? s3[t - o] : 0;
        __syncthreads();
        s3[t] += v;
        __syncthreads();
    }
    if (i < N) {
        g_off[i] = g_part[b] + s3[t] - c;
        if (i == N - 1) g_off[N] = E;
        g_cnt[i] = 0;  // reset for fill cursor
    }
}

// ---------------------------------------------------------------- CSR: fill (4 edges/thread)
__global__ void fillk(const int* __restrict__ src, const int* __restrict__ dst, int E) {
    int e4 = (blockIdx.x * blockDim.x + threadIdx.x) * 4;
    if (e4 >= E) return;
    if (e4 + 4 <= E) {
        int4 d = *(const int4*)&dst[e4];
        int4 s = *(const int4*)&src[e4];
        int p0 = g_off[d.x] + atomicAdd(&g_cnt[d.x], 1);
        int p1 = g_off[d.y] + atomicAdd(&g_cnt[d.y], 1);
        int p2 = g_off[d.z] + atomicAdd(&g_cnt[d.z], 1);
        int p3 = g_off[d.w] + atomicAdd(&g_cnt[d.w], 1);
        g_esrc[p0] = s.x;
        g_esrc[p1] = s.y;
        g_esrc[p2] = s.z;
        g_esrc[p3] = s.w;
    } else {
        for (int e = e4; e < E; e++) {
            int d = __ldg(&dst[e]);
            int pos = g_off[d] + atomicAdd(&g_cnt[d], 1);
            g_esrc[pos] = __ldg(&src[e]);
        }
    }
}

// ---------------------------------------------------------------- fused softmax + aggregate
// One warp per dst node, single pass, no max subtraction (|logit| << 88).
// Indices preloaded coalesced and broadcast via shfl; 4 edges in flight.
__global__ void aggk(float* __restrict__ out, int N) {
    int w = (blockIdx.x * blockDim.x + threadIdx.x) >> 5;
    if (w >= N) return;
    int lane = threadIdx.x & 31;
    int lo = g_off[w], hi = g_off[w + 1];

    int hh = lane >> 2;  // 4 lanes per head; lane owns cols lane*4..+3
    float s2d = g_s2[(size_t)w * 8 + hh];

    float4 acc = make_float4(0.f, 0.f, 0.f, 0.f);
    float z = 0.f;

    for (int base = lo; base < hi; base += 32) {
        int nb = min(32, hi - base);
        int myidx = 0;
        if (base + lane < hi) myidx = g_esrc[base + lane];

        int j = 0;
        for (; j + 4 <= nb; j += 4) {
            int s0 = __shfl_sync(0xffffffffu, myidx, j);
            int s1i = __shfl_sync(0xffffffffu, myidx, j + 1);
            int s2i = __shfl_sync(0xffffffffu, myidx, j + 2);
            int s3i = __shfl_sync(0xffffffffu, myidx, j + 3);
            float x0 = g_s1[(size_t)s0 * 8 + hh];
            float x1 = g_s1[(size_t)s1i * 8 + hh];
            float x2 = g_s1[(size_t)s2i * 8 + hh];
            float x3 = g_s1[(size_t)s3i * 8 + hh];
            uint2 r0 = *(const uint2*)&g_whh[(size_t)s0 * 128 + lane * 4];
            uint2 r1 = *(const uint2*)&g_whh[(size_t)s1i * 128 + lane * 4];
            uint2 r2 = *(const uint2*)&g_whh[(size_t)s2i * 128 + lane * 4];
            uint2 r3 = *(const uint2*)&g_whh[(size_t)s3i * 128 + lane * 4];
            float e0 = __expf(lrelu(x0 + s2d));
            float e1 = __expf(lrelu(x1 + s2d));
            float e2 = __expf(lrelu(x2 + s2d));
            float e3 = __expf(lrelu(x3 + s2d));
            float2 f;
            f = __half22float2(*(__half2*)&r0.x); acc.x += e0 * f.x; acc.y += e0 * f.y;
            f = __half22float2(*(__half2*)&r0.y); acc.z += e0 * f.x; acc.w += e0 * f.y;
            f = __half22float2(*(__half2*)&r1.x); acc.x += e1 * f.x; acc.y += e1 * f.y;
            f = __half22float2(*(__half2*)&r1.y); acc.z += e1 * f.x; acc.w += e1 * f.y;
            f = __half22float2(*(__half2*)&r2.x); acc.x += e2 * f.x; acc.y += e2 * f.y;
            f = __half22float2(*(__half2*)&r2.y); acc.z += e2 * f.x; acc.w += e2 * f.y;
            f = __half22float2(*(__half2*)&r3.x); acc.x += e3 * f.x; acc.y += e3 * f.y;
            f = __half22float2(*(__half2*)&r3.y); acc.z += e3 * f.x; acc.w += e3 * f.y;
            z += e0 + e1 + e2 + e3;
        }
        for (; j < nb; j++) {
            int s = __shfl_sync(0xffffffffu, myidx, j);
            float a = __expf(lrelu(g_s1[(size_t)s * 8 + hh] + s2d));
            uint2 r = *(const uint2*)&g_whh[(size_t)s * 128 + lane * 4];
            float2 f0 = __half22float2(*(__half2*)&r.x);
            float2 f1 = __half22float2(*(__half2*)&r.y);
            acc.x += a * f0.x;
            acc.y += a * f0.y;
            acc.z += a * f1.x;
            acc.w += a * f1.y;
            z += a;
        }
    }
    float rz = 1.0f / fmaxf(z, 1e-16f);
    float4 o = make_float4(acc.x * rz, acc.y * rz, acc.z * rz, acc.w * rz);
    *(float4*)&out[(size_t)w * 128 + lane * 4] = o;
}

// ---------------------------------------------------------------- launch
extern "C" void kernel_launch(void* const* d_in, const int* in_sizes, int n_in,
                              void* d_out, int out_size) {
    const float* h   = (const float*)d_in[0];
    const int*   src = (const int*)d_in[1];
    const int*   dst = (const int*)d_in[2];
    const float* W   = (const float*)d_in[3];
    const float* a1  = (const float*)d_in[4];
    const float* a2  = (const float*)d_in[5];
    float* out = (float*)d_out;

    int N = in_sizes[0] / 128;
    int E = in_sizes[1];

    const int SMEM = (16384 + 16384) * 4;  // 128 KB dynamic smem
    cudaFuncSetAttribute(projk, cudaFuncAttributeMaxDynamicSharedMemorySize, SMEM);

    int nb = (N + 255) / 256;
    int ne4 = (E + 3) / 4;

    zcntk<<<(N + 255) / 256, 256>>>(N);
    projk<<<(N + 127) / 128, 256, SMEM>>>(h, W, a1, a2, N);
    countk<<<(ne4 + 255) / 256, 256>>>(dst, E);
    scan1k<<<nb, 256>>>(N);
    scan2k<<<1, 512>>>(nb);
    scan3k<<<nb, 256>>>(N, E);
    fillk<<<(ne4 + 255) / 256, 256>>>(src, dst, E);
    aggk<<<(N * 32 + 255) / 256, 256>>>(out, N);
}

// round 11
// speedup vs baseline: 1.0088x; 1.0088x over previous
#include <cuda_runtime.h>
#include <cuda_fp16.h>

#define ALPHA 0.2f
#define MAXN 100000
#define MAXE 1600000
// F=128, H=8, D=16, C=H*D=128

__device__ __half g_whh[(size_t)MAXN * 128]; // projected features [N][128] fp16
__device__ float  g_s1[(size_t)MAXN * 8];
__device__ float  g_s2[(size_t)MAXN * 8];
__device__ int    g_cnt[MAXN];               // per-dst counts / fill cursor
__device__ int    g_off[MAXN + 1];           // CSR offsets by dst
__device__ int    g_esrc[MAXE];              // src node id per CSR slot
__device__ int    g_part[512];               // scan partials

__device__ __forceinline__ float lrelu(float x) {
    return x > 0.f ? x : ALPHA * x;
}

// ---------------------------------------------------------------- zero counts
__global__ void zcntk(int N) {
    int i = blockIdx.x * blockDim.x + threadIdx.x;
    if (i < N) g_cnt[i] = 0;
}

// ---------------------------------------------------------------- projection + fused s1/s2
// 128 nodes per block, 256 threads, 8x8 register tile per thread (scalar FFMA).
__global__ void __launch_bounds__(256) projk(const float* __restrict__ h,
                                             const float* __restrict__ W,
                                             const float* __restrict__ a1,
                                             const float* __restrict__ a2,
                                             int N) {
    extern __shared__ float sm[];
    float* ws  = sm;            // 16384 floats: W transposed [k][c]
    float* hst = sm + 16384;    // 16384 floats: h transposed [k][n_local]
    int tid = threadIdx.x;
    int n0 = blockIdx.x * 128;

    for (int idx = tid; idx < 16384; idx += 256) {
        int k = idx >> 7, c = idx & 127;
        ws[idx] = W[(c >> 4) * 2048 + k * 16 + (c & 15)];
    }
    {
        int i = tid >> 1, kh = tid & 1;   // node i, k-half kh
        int n = n0 + i;
#pragma unroll
        for (int j = 0; j < 16; j++) {
            int k = kh * 64 + j * 4;
            float4 v = make_float4(0.f, 0.f, 0.f, 0.f);
            if (n < N) v = *(const float4*)&h[(size_t)n * 128 + k];
            hst[(k + 0) * 128 + i] = v.x;
            hst[(k + 1) * 128 + i] = v.y;
            hst[(k + 2) * 128 + i] = v.z;
            hst[(k + 3) * 128 + i] = v.w;
        }
    }
    __syncthreads();

    int cg = tid & 15;   // cols cg*8 .. cg*8+7
    int ng = tid >> 4;   // nodes ng*8 .. ng*8+7
    float acc[8][8];
#pragma unroll
    for (int i = 0; i < 8; i++)
#pragma unroll
        for (int j = 0; j < 8; j++) acc[i][j] = 0.0f;

#pragma unroll 2
    for (int k = 0; k < 128; k++) {
        float4 w0 = *(float4*)&ws[k * 128 + cg * 8];
        float4 w1 = *(float4*)&ws[k * 128 + cg * 8 + 4];
        float4 h0 = *(float4*)&hst[k * 128 + ng * 8];
        float4 h1 = *(float4*)&hst[k * 128 + ng * 8 + 4];
        float hv[8] = {h0.x, h0.y, h0.z, h0.w, h1.x, h1.y, h1.z, h1.w};
        float wv[8] = {w0.x, w0.y, w0.z, w0.w, w1.x, w1.y, w1.z, w1.w};
#pragma unroll
        for (int i = 0; i < 8; i++)
#pragma unroll
            for (int j = 0; j < 8; j++) acc[i][j] += hv[i] * wv[j];
    }

    // epilogue: store Wh (fp16) + fused s1/s2 (head = cg>>1, half = cg&1)
    int head = cg >> 1;
    float a1v[8], a2v[8];
#pragma unroll
    for (int j = 0; j < 8; j++) {
        a1v[j] = __ldg(&a1[head * 16 + (cg & 1) * 8 + j]);
        a2v[j] = __ldg(&a2[head * 16 + (cg & 1) * 8 + j]);
    }
#pragma unroll
    for (int i = 0; i < 8; i++) {
        float p1 = 0.f, p2 = 0.f;
#pragma unroll
        for (int j = 0; j < 8; j++) {
            p1 += acc[i][j] * a1v[j];
            p2 += acc[i][j] * a2v[j];
        }
        p1 += __shfl_xor_sync(0xffffffffu, p1, 1);
        p2 += __shfl_xor_sync(0xffffffffu, p2, 1);
        int n = n0 + ng * 8 + i;
        if (n < N) {
            __half2 q[4];
#pragma unroll
            for (int j = 0; j < 4; j++)
                q[j] = __floats2half2_rn(acc[i][2 * j], acc[i][2 * j + 1]);
            *(uint4*)&g_whh[(size_t)n * 128 + cg * 8] = *(uint4*)q;
            if (!(cg & 1)) {
                g_s1[(size_t)n * 8 + head] = p1;
                g_s2[(size_t)n * 8 + head] = p2;
            }
        }
    }
}

// ---------------------------------------------------------------- CSR: count (4 edges/thread)
__global__ void countk(const int* __restrict__ dst, int E) {
    int e4 = (blockIdx.x * blockDim.x + threadIdx.x) * 4;
    if (e4 >= E) return;
    if (e4 + 4 <= E) {
        int4 d = *(const int4*)&dst[e4];
        atomicAdd(&g_cnt[d.x], 1);
        atomicAdd(&g_cnt[d.y], 1);
        atomicAdd(&g_cnt[d.z], 1);
        atomicAdd(&g_cnt[d.w], 1);
    } else {
        for (int e = e4; e < E; e++) atomicAdd(&g_cnt[__ldg(&dst[e])], 1);
    }
}

// ---------------------------------------------------------------- scan stage 1: block sums
__global__ void scan1k(int N) {
    __shared__ int wsum[8];
    int b = blockIdx.x;
    int i = b * 256 + threadIdx.x;
    int v = (i < N) ? g_cnt[i] : 0;
#pragma unroll
    for (int o = 16; o; o >>= 1) v += __shfl_down_sync(0xffffffffu, v, o);
    if ((threadIdx.x & 31) == 0) wsum[threadIdx.x >> 5] = v;
    __syncthreads();
    if (threadIdx.x == 0) {
        int s = 0;
#pragma unroll
        for (int k = 0; k < 8; k++) s += wsum[k];
        g_part[b] = s;
    }
}

// ---------------------------------------------------------------- scan stage 2: scan partials (1 block)
__global__ void scan2k(int nb) {
    __shared__ int s2[512];
    int t = threadIdx.x;
    s2[t] = (t < nb) ? g_part[t] : 0;
    __syncthreads();
    for (int o = 1; o < 512; o <<= 1) {
        int v = (t >= o) ? s2[t - o] : 0;
        __syncthreads();
        s2[t] += v;
        __syncthreads();
    }
    if (t < nb) g_part[t] = t ? s2[t - 1] : 0;  // exclusive
}

// ---------------------------------------------------------------- scan stage 3: offsets + cursor reset
__global__ void scan3k(int N, int E) {
    __shared__ int s3[256];
    int b = blockIdx.x, t = threadIdx.x;
    int i = b * 256 + t;
    int c = (i < N) ? g_cnt[i] : 0;
    s3[t] = c;
    __syncthreads();
    for (int o = 1; o < 256; o <<= 1) {
        int v = (t >= o) ? s3[t - o] : 0;
        __syncthreads();
        s3[t] += v;
        __syncthreads();
    }
    if (i < N) {
        g_off[i] = g_part[b] + s3[t] - c;
        if (i == N - 1) g_off[N] = E;
        g_cnt[i] = 0;  // reset for fill cursor
    }
}

// ---------------------------------------------------------------- CSR: fill (4 edges/thread)
__global__ void fillk(const int* __restrict__ src, const int* __restrict__ dst, int E) {
    int e4 = (blockIdx.x * blockDim.x + threadIdx.x) * 4;
    if (e4 >= E) return;
    if (e4 + 4 <= E) {
        int4 d = *(const int4*)&dst[e4];
        int4 s = *(const int4*)&src[e4];
        int p0 = g_off[d.x] + atomicAdd(&g_cnt[d.x], 1);
        int p1 = g_off[d.y] + atomicAdd(&g_cnt[d.y], 1);
        int p2 = g_off[d.z] + atomicAdd(&g_cnt[d.z], 1);
        int p3 = g_off[d.w] + atomicAdd(&g_cnt[d.w], 1);
        g_esrc[p0] = s.x;
        g_esrc[p1] = s.y;
        g_esrc[p2] = s.z;
        g_esrc[p3] = s.w;
    } else {
        for (int e = e4; e < E; e++) {
            int d = __ldg(&dst[e]);
            int pos = g_off[d] + atomicAdd(&g_cnt[d], 1);
            g_esrc[pos] = __ldg(&src[e]);
        }
    }
}

// ---------------------------------------------------------------- fused softmax + aggregate
// One warp per dst node, single pass, no max subtraction (|logit| << 88).
// Indices preloaded coalesced and broadcast via shfl; 4 edges in flight.
__global__ void aggk(float* __restrict__ out, int N) {
    int w = (blockIdx.x * blockDim.x + threadIdx.x) >> 5;
    if (w >= N) return;
    int lane = threadIdx.x & 31;
    int lo = g_off[w], hi = g_off[w + 1];

    int hh = lane >> 2;  // 4 lanes per head; lane owns cols lane*4..+3
    float s2d = g_s2[(size_t)w * 8 + hh];

    float4 acc = make_float4(0.f, 0.f, 0.f, 0.f);
    float z = 0.f;

    for (int base = lo; base < hi; base += 32) {
        int nb = min(32, hi - base);
        int myidx = 0;
        if (base + lane < hi) myidx = g_esrc[base + lane];

        int j = 0;
        for (; j + 4 <= nb; j += 4) {
            int s0 = __shfl_sync(0xffffffffu, myidx, j);
            int s1i = __shfl_sync(0xffffffffu, myidx, j + 1);
            int s2i = __shfl_sync(0xffffffffu, myidx, j + 2);
            int s3i = __shfl_sync(0xffffffffu, myidx, j + 3);
            float x0 = g_s1[(size_t)s0 * 8 + hh];
            float x1 = g_s1[(size_t)s1i * 8 + hh];
            float x2 = g_s1[(size_t)s2i * 8 + hh];
            float x3 = g_s1[(size_t)s3i * 8 + hh];
            uint2 r0 = *(const uint2*)&g_whh[(size_t)s0 * 128 + lane * 4];
            uint2 r1 = *(const uint2*)&g_whh[(size_t)s1i * 128 + lane * 4];
            uint2 r2 = *(const uint2*)&g_whh[(size_t)s2i * 128 + lane * 4];
            uint2 r3 = *(const uint2*)&g_whh[(size_t)s3i * 128 + lane * 4];
            float e0 = __expf(lrelu(x0 + s2d));
            float e1 = __expf(lrelu(x1 + s2d));
            float e2 = __expf(lrelu(x2 + s2d));
            float e3 = __expf(lrelu(x3 + s2d));
            float2 f;
            f = __half22float2(*(__half2*)&r0.x); acc.x += e0 * f.x; acc.y += e0 * f.y;
            f = __half22float2(*(__half2*)&r0.y); acc.z += e0 * f.x; acc.w += e0 * f.y;
            f = __half22float2(*(__half2*)&r1.x); acc.x += e1 * f.x; acc.y += e1 * f.y;
            f = __half22float2(*(__half2*)&r1.y); acc.z += e1 * f.x; acc.w += e1 * f.y;
            f = __half22float2(*(__half2*)&r2.x); acc.x += e2 * f.x; acc.y += e2 * f.y;
            f = __half22float2(*(__half2*)&r2.y); acc.z += e2 * f.x; acc.w += e2 * f.y;
            f = __half22float2(*(__half2*)&r3.x); acc.x += e3 * f.x; acc.y += e3 * f.y;
            f = __half22float2(*(__half2*)&r3.y); acc.z += e3 * f.x; acc.w += e3 * f.y;
            z += e0 + e1 + e2 + e3;
        }
        for (; j < nb; j++) {
            int s = __shfl_sync(0xffffffffu, myidx, j);
            float a = __expf(lrelu(g_s1[(size_t)s * 8 + hh] + s2d));
            uint2 r = *(const uint2*)&g_whh[(size_t)s * 128 + lane * 4];
            float2 f0 = __half22float2(*(__half2*)&r.x);
            float2 f1 = __half22float2(*(__half2*)&r.y);
            acc.x += a * f0.x;
            acc.y += a * f0.y;
            acc.z += a * f1.x;
            acc.w += a * f1.y;
            z += a;
        }
    }
    float rz = 1.0f / fmaxf(z, 1e-16f);
    float4 o = make_float4(acc.x * rz, acc.y * rz, acc.z * rz, acc.w * rz);
    *(float4*)&out[(size_t)w * 128 + lane * 4] = o;
}

// ---------------------------------------------------------------- launch
extern "C" void kernel_launch(void* const* d_in, const int* in_sizes, int n_in,
                              void* d_out, int out_size) {
    const float* h   = (const float*)d_in[0];
    const int*   src = (const int*)d_in[1];
    const int*   dst = (const int*)d_in[2];
    const float* W   = (const float*)d_in[3];
    const float* a1  = (const float*)d_in[4];
    const float* a2  = (const float*)d_in[5];
    float* out = (float*)d_out;

    int N = in_sizes[0] / 128;
    int E = in_sizes[1];

    const int SMEM = (16384 + 16384) * 4;  // 128 KB dynamic smem
    cudaFuncSetAttribute(projk, cudaFuncAttributeMaxDynamicSharedMemorySize, SMEM);

    int nb = (N + 255) / 256;
    int ne4 = (E + 3) / 4;

    zcntk<<<(N + 255) / 256, 256>>>(N);
    projk<<<(N + 127) / 128, 256, SMEM>>>(h, W, a1, a2, N);
    countk<<<(ne4 + 255) / 256, 256>>>(dst, E);
    scan1k<<<nb, 256>>>(N);
    scan2k<<<1, 512>>>(nb);
    scan3k<<<nb, 256>>>(N, E);
    fillk<<<(ne4 + 255) / 256, 256>>>(src, dst, E);
    aggk<<<(N * 32 + 255) / 256, 256>>>(out, N);
}

// round 14
// speedup vs baseline: 1.0598x; 1.0506x over previous
#include <cuda_runtime.h>
#include <cuda_fp16.h>

#define ALPHA 0.2f
#define MAXN 100000
#define MAXE 1600000
// F=128, H=8, D=16, C=H*D=128

__device__ __half g_whh[(size_t)MAXN * 128]; // projected features [N][128] fp16
__device__ float  g_s1[(size_t)MAXN * 8];
__device__ float  g_s2[(size_t)MAXN * 8];
__device__ int    g_cnt[MAXN];               // per-dst counts / fill cursor
__device__ int    g_off[MAXN + 1];           // CSR offsets by dst
__device__ int    g_esrc[MAXE];              // src node id per CSR slot
__device__ int    g_part[512];               // scan partials

__device__ __forceinline__ float lrelu(float x) {
    return x > 0.f ? x : ALPHA * x;
}

// ---------------------------------------------------------------- zero counts
__global__ void zcntk(int N) {
    int i = blockIdx.x * blockDim.x + threadIdx.x;
    if (i < N) g_cnt[i] = 0;
}

// ---------------------------------------------------------------- projection + fused s1/s2
// 128 nodes per block, 256 threads, 8x8 register tile per thread (scalar FFMA).
__global__ void __launch_bounds__(256) projk(const float* __restrict__ h,
                                             const float* __restrict__ W,
                                             const float* __restrict__ a1,
                                             const float* __restrict__ a2,
                                             int N) {
    extern __shared__ float sm[];
    float* ws  = sm;            // 16384 floats: W transposed [k][c]
    float* hst = sm + 16384;    // 16384 floats: h transposed [k][n_local]
    int tid = threadIdx.x;
    int n0 = blockIdx.x * 128;

    for (int idx = tid; idx < 16384; idx += 256) {
        int k = idx >> 7, c = idx & 127;
        ws[idx] = W[(c >> 4) * 2048 + k * 16 + (c & 15)];
    }
    {
        int i = tid >> 1, kh = tid & 1;   // node i, k-half kh
        int n = n0 + i;
#pragma unroll
        for (int j = 0; j < 16; j++) {
            int k = kh * 64 + j * 4;
            float4 v = make_float4(0.f, 0.f, 0.f, 0.f);
            if (n < N) v = *(const float4*)&h[(size_t)n * 128 + k];
            hst[(k + 0) * 128 + i] = v.x;
            hst[(k + 1) * 128 + i] = v.y;
            hst[(k + 2) * 128 + i] = v.z;
            hst[(k + 3) * 128 + i] = v.w;
        }
    }
    __syncthreads();

    int cg = tid & 15;   // cols cg*8 .. cg*8+7
    int ng = tid >> 4;   // nodes ng*8 .. ng*8+7
    float acc[8][8];
#pragma unroll
    for (int i = 0; i < 8; i++)
#pragma unroll
        for (int j = 0; j < 8; j++) acc[i][j] = 0.0f;

#pragma unroll 2
    for (int k = 0; k < 128; k++) {
        float4 w0 = *(float4*)&ws[k * 128 + cg * 8];
        float4 w1 = *(float4*)&ws[k * 128 + cg * 8 + 4];
        float4 h0 = *(float4*)&hst[k * 128 + ng * 8];
        float4 h1 = *(float4*)&hst[k * 128 + ng * 8 + 4];
        float hv[8] = {h0.x, h0.y, h0.z, h0.w, h1.x, h1.y, h1.z, h1.w};
        float wv[8] = {w0.x, w0.y, w0.z, w0.w, w1.x, w1.y, w1.z, w1.w};
#pragma unroll
        for (int i = 0; i < 8; i++)
#pragma unroll
            for (int j = 0; j < 8; j++) acc[i][j] += hv[i] * wv[j];
    }

    // epilogue: store Wh (fp16) + fused s1/s2 (head = cg>>1, half = cg&1)
    int head = cg >> 1;
    float a1v[8], a2v[8];
#pragma unroll
    for (int j = 0; j < 8; j++) {
        a1v[j] = __ldg(&a1[head * 16 + (cg & 1) * 8 + j]);
        a2v[j] = __ldg(&a2[head * 16 + (cg & 1) * 8 + j]);
    }
#pragma unroll
    for (int i = 0; i < 8; i++) {
        float p1 = 0.f, p2 = 0.f;
#pragma unroll
        for (int j = 0; j < 8; j++) {
            p1 += acc[i][j] * a1v[j];
            p2 += acc[i][j] * a2v[j];
        }
        p1 += __shfl_xor_sync(0xffffffffu, p1, 1);
        p2 += __shfl_xor_sync(0xffffffffu, p2, 1);
        int n = n0 + ng * 8 + i;
        if (n < N) {
            __half2 q[4];
#pragma unroll
            for (int j = 0; j < 4; j++)
                q[j] = __floats2half2_rn(acc[i][2 * j], acc[i][2 * j + 1]);
            *(uint4*)&g_whh[(size_t)n * 128 + cg * 8] = *(uint4*)q;
            if (!(cg & 1)) {
                g_s1[(size_t)n * 8 + head] = p1;
                g_s2[(size_t)n * 8 + head] = p2;
            }
        }
    }
}

// ---------------------------------------------------------------- CSR: count
__global__ void countk(const int* __restrict__ dst, int E) {
    int e = blockIdx.x * blockDim.x + threadIdx.x;
    if (e >= E) return;
    atomicAdd(&g_cnt[__ldg(&dst[e])], 1);
}

// ---------------------------------------------------------------- scan stage 1: block sums
__global__ void scan1k(int N) {
    __shared__ int wsum[8];
    int b = blockIdx.x;
    int i = b * 256 + threadIdx.x;
    int v = (i < N) ? g_cnt[i] : 0;
#pragma unroll
    for (int o = 16; o; o >>= 1) v += __shfl_down_sync(0xffffffffu, v, o);
    if ((threadIdx.x & 31) == 0) wsum[threadIdx.x >> 5] = v;
    __syncthreads();
    if (threadIdx.x == 0) {
        int s = 0;
#pragma unroll
        for (int k = 0; k < 8; k++) s += wsum[k];
        g_part[b] = s;
    }
}

// ---------------------------------------------------------------- scan stage 2: scan partials (1 block)
__global__ void scan2k(int nb) {
    __shared__ int s2[512];
    int t = threadIdx.x;
    s2[t] = (t < nb) ? g_part[t] : 0;
    __syncthreads();
    for (int o = 1; o < 512; o <<= 1) {
        int v = (t >= o) ? s2[t - o] : 0;
        __syncthreads();
        s2[t] += v;
        __syncthreads();
    }
    if (t < nb) g_part[t] = t ? s2[t - 1] : 0;  // exclusive
}

// ---------------------------------------------------------------- scan stage 3: offsets + cursor reset
__global__ void scan3k(int N, int E) {
    __shared__ int s3[256];
    int b = blockIdx.x, t = threadIdx.x;
    int i = b * 256 + t;
    int c = (i < N) ? g_cnt[i] : 0;
    s3[t] = c;
    __syncthreads();
    for (int o = 1; o < 256; o <<= 1) {
        int v = (t >= o) ? s3[t - o] : 0;
        __syncthreads();
        s3[t] += v;
        __syncthreads();
    }
    if (i < N) {
        g_off[i] = g_part[b] + s3[t] - c;
        if (i == N - 1) g_off[N] = E;
        g_cnt[i] = 0;  // reset for fill cursor
    }
}

// ---------------------------------------------------------------- CSR: fill
__global__ void fillk(const int* __restrict__ src, const int* __restrict__ dst, int E) {
    int e = blockIdx.x * blockDim.x + threadIdx.x;
    if (e >= E) return;
    int d = __ldg(&dst[e]);
    int pos = g_off[d] + atomicAdd(&g_cnt[d], 1);
    g_esrc[pos] = __ldg(&src[e]);
}

// ---------------------------------------------------------------- fused softmax + aggregate
// One warp per dst node, single pass, no max subtraction (|logit| << 88).
// Direct edge-list loads (as R6), 4 edges in flight for MLP.
__global__ void aggk(float* __restrict__ out, int N) {
    int w = (blockIdx.x * blockDim.x + threadIdx.x) >> 5;
    if (w >= N) return;
    int lane = threadIdx.x & 31;
    int lo = g_off[w], hi = g_off[w + 1];

    int hh = lane >> 2;  // 4 lanes per head; lane owns cols lane*4..+3
    float s2d = g_s2[(size_t)w * 8 + hh];

    float4 acc = make_float4(0.f, 0.f, 0.f, 0.f);
    float z = 0.f;
    int i = lo;
    for (; i + 4 <= hi; i += 4) {
        int s0 = g_esrc[i];
        int s1i = g_esrc[i + 1];
        int s2i = g_esrc[i + 2];
        int s3i = g_esrc[i + 3];
        float x0 = g_s1[(size_t)s0 * 8 + hh];
        float x1 = g_s1[(size_t)s1i * 8 + hh];
        float x2 = g_s1[(size_t)s2i * 8 + hh];
        float x3 = g_s1[(size_t)s3i * 8 + hh];
        uint2 r0 = *(const uint2*)&g_whh[(size_t)s0 * 128 + lane * 4];
        uint2 r1 = *(const uint2*)&g_whh[(size_t)s1i * 128 + lane * 4];
        uint2 r2 = *(const uint2*)&g_whh[(size_t)s2i * 128 + lane * 4];
        uint2 r3 = *(const uint2*)&g_whh[(size_t)s3i * 128 + lane * 4];
        float e0 = __expf(lrelu(x0 + s2d));
        float e1 = __expf(lrelu(x1 + s2d));
        float e2 = __expf(lrelu(x2 + s2d));
        float e3 = __expf(lrelu(x3 + s2d));
        float2 f;
        f = __half22float2(*(__half2*)&r0.x); acc.x += e0 * f.x; acc.y += e0 * f.y;
        f = __half22float2(*(__half2*)&r0.y); acc.z += e0 * f.x; acc.w += e0 * f.y;
        f = __half22float2(*(__half2*)&r1.x); acc.x += e1 * f.x; acc.y += e1 * f.y;
        f = __half22float2(*(__half2*)&r1.y); acc.z += e1 * f.x; acc.w += e1 * f.y;
        f = __half22float2(*(__half2*)&r2.x); acc.x += e2 * f.x; acc.y += e2 * f.y;
        f = __half22float2(*(__half2*)&r2.y); acc.z += e2 * f.x; acc.w += e2 * f.y;
        f = __half22float2(*(__half2*)&r3.x); acc.x += e3 * f.x; acc.y += e3 * f.y;
        f = __half22float2(*(__half2*)&r3.y); acc.z += e3 * f.x; acc.w += e3 * f.y;
        z += e0 + e1 + e2 + e3;
    }
    for (; i < hi; i++) {
        int s = g_esrc[i];
        float a = __expf(lrelu(g_s1[(size_t)s * 8 + hh] + s2d));
        uint2 r = *(const uint2*)&g_whh[(size_t)s * 128 + lane * 4];
        float2 f0 = __half22float2(*(__half2*)&r.x);
        float2 f1 = __half22float2(*(__half2*)&r.y);
        acc.x += a * f0.x;
        acc.y += a * f0.y;
        acc.z += a * f1.x;
        acc.w += a * f1.y;
        z += a;
    }
    float rz = 1.0f / fmaxf(z, 1e-16f);
    float4 o = make_float4(acc.x * rz, acc.y * rz, acc.z * rz, acc.w * rz);
    *(float4*)&out[(size_t)w * 128 + lane * 4] = o;
}

// ---------------------------------------------------------------- launch
extern "C" void kernel_launch(void* const* d_in, const int* in_sizes, int n_in,
                              void* d_out, int out_size) {
    const float* h   = (const float*)d_in[0];
    const int*   src = (const int*)d_in[1];
    const int*   dst = (const int*)d_in[2];
    const float* W   = (const float*)d_in[3];
    const float* a1  = (const float*)d_in[4];
    const float* a2  = (const float*)d_in[5];
    float* out = (float*)d_out;

    int N = in_sizes[0] / 128;
    int E = in_sizes[1];

    const int SMEM = (16384 + 16384) * 4;  // 128 KB dynamic smem
    cudaFuncSetAttribute(projk, cudaFuncAttributeMaxDynamicSharedMemorySize, SMEM);

    int nb = (N + 255) / 256;

    zcntk<<<(N + 255) / 256, 256>>>(N);
    projk<<<(N + 127) / 128, 256, SMEM>>>(h, W, a1, a2, N);
    countk<<<(E + 255) / 256, 256>>>(dst, E);
    scan1k<<<nb, 256>>>(N);
    scan2k<<<1, 512>>>(nb);
    scan3k<<<nb, 256>>>(N, E);
    fillk<<<(E + 255) / 256, 256>>>(src, dst, E);
    aggk<<<(N * 32 + 255) / 256, 256>>>(out, N);
}